// round 1
// baseline (speedup 1.0000x reference)
#include <cuda_runtime.h>

// Causal multi-head attention, fp32, flash-attention structure.
// Shapes fixed by the problem: B=2, H=16, S=2048, D=64.
// Mask input (d_in[3]) is the causal tril -> handled analytically, not read.

#define BH_TOTAL 32      // B*H
#define SEQ      2048
#define HDIM     64
#define BM       128     // query rows per block (one thread per row)
#define BN       64      // kv rows per shared tile
#define NTHREADS 128

__global__ __launch_bounds__(NTHREADS)
void fa_causal_fp32_kernel(const float* __restrict__ Q,
                           const float* __restrict__ K,
                           const float* __restrict__ V,
                           float* __restrict__ O)
{
    const int nmb  = SEQ / BM;              // 16 m-blocks per head
    const int mblk = blockIdx.x % nmb;
    const int bh   = blockIdx.x / nmb;
    const int tid  = threadIdx.x;
    const int row  = mblk * BM + tid;       // query row owned by this thread

    const float* Qb = Q + bh * SEQ * HDIM;
    const float* Kb = K + bh * SEQ * HDIM;
    const float* Vb = V + bh * SEQ * HDIM;
    float*       Ob = O + bh * SEQ * HDIM;

    __shared__ float Ksh[BN * HDIM];
    __shared__ float Vsh[BN * HDIM];

    // Load this thread's Q row, pre-scaled by 1/sqrt(D) = 0.125
    float q[HDIM];
    #pragma unroll
    for (int d = 0; d < HDIM; d += 4) {
        float4 t = *reinterpret_cast<const float4*>(Qb + row * HDIM + d);
        q[d + 0] = t.x * 0.125f;
        q[d + 1] = t.y * 0.125f;
        q[d + 2] = t.z * 0.125f;
        q[d + 3] = t.w * 0.125f;
    }

    float acc[HDIM];
    #pragma unroll
    for (int d = 0; d < HDIM; ++d) acc[d] = 0.0f;
    float m = -1e30f;   // running max
    float l = 0.0f;     // running denominator

    const int n_tiles    = (mblk * BM + BM) / BN;  // kv tiles this block needs
    const int full_tiles = (mblk * BM) / BN;       // tiles fully below diagonal

    for (int t = 0; t < n_tiles; ++t) {
        const float* Kt = Kb + t * BN * HDIM;
        const float* Vt = Vb + t * BN * HDIM;

        __syncthreads();
        #pragma unroll
        for (int i = 0; i < (BN * HDIM) / (NTHREADS * 4); ++i) {  // 8 float4 per thread
            int idx = (i * NTHREADS + tid) * 4;
            *reinterpret_cast<float4*>(Ksh + idx) =
                *reinterpret_cast<const float4*>(Kt + idx);
            *reinterpret_cast<float4*>(Vsh + idx) =
                *reinterpret_cast<const float4*>(Vt + idx);
        }
        __syncthreads();

        const bool diag = (t >= full_tiles);
        const int  kv0  = t * BN;

        #pragma unroll 1
        for (int j = 0; j < BN; ++j) {
            // s = q . K[j]  (4 independent accumulators to break the FFMA chain)
            float s0 = 0.f, s1 = 0.f, s2 = 0.f, s3 = 0.f;
            #pragma unroll
            for (int d = 0; d < HDIM; d += 8) {
                float4 a = *reinterpret_cast<const float4*>(Ksh + j * HDIM + d);
                float4 b = *reinterpret_cast<const float4*>(Ksh + j * HDIM + d + 4);
                s0 = fmaf(q[d + 0], a.x, s0);
                s1 = fmaf(q[d + 1], a.y, s1);
                s2 = fmaf(q[d + 2], a.z, s2);
                s3 = fmaf(q[d + 3], a.w, s3);
                s0 = fmaf(q[d + 4], b.x, s0);
                s1 = fmaf(q[d + 5], b.y, s1);
                s2 = fmaf(q[d + 6], b.z, s2);
                s3 = fmaf(q[d + 7], b.w, s3);
            }
            float s = (s0 + s1) + (s2 + s3);
            if (diag && (kv0 + j > row)) s = -1e30f;  // causal mask (diag tiles only)

            // Online softmax; rescale path is rare (~ln(S) times per row)
            float m_new = fmaxf(m, s);
            if (m_new > m) {
                float alpha = __expf(m - m_new);
                l *= alpha;
                #pragma unroll
                for (int d = 0; d < HDIM; ++d) acc[d] *= alpha;
                m = m_new;
            }
            float p = __expf(s - m);   // masked entries: exp(-1e30 - m) == 0 exactly
            l += p;

            #pragma unroll
            for (int d = 0; d < HDIM; d += 4) {
                float4 v = *reinterpret_cast<const float4*>(Vsh + j * HDIM + d);
                acc[d + 0] = fmaf(p, v.x, acc[d + 0]);
                acc[d + 1] = fmaf(p, v.y, acc[d + 1]);
                acc[d + 2] = fmaf(p, v.z, acc[d + 2]);
                acc[d + 3] = fmaf(p, v.w, acc[d + 3]);
            }
        }
    }

    const float inv_l = 1.0f / l;
    #pragma unroll
    for (int d = 0; d < HDIM; d += 4) {
        float4 o;
        o.x = acc[d + 0] * inv_l;
        o.y = acc[d + 1] * inv_l;
        o.z = acc[d + 2] * inv_l;
        o.w = acc[d + 3] * inv_l;
        *reinterpret_cast<float4*>(Ob + row * HDIM + d) = o;
    }
}

extern "C" void kernel_launch(void* const* d_in, const int* in_sizes, int n_in,
                              void* d_out, int out_size)
{
    const float* Q = (const float*)d_in[0];
    const float* K = (const float*)d_in[1];
    const float* V = (const float*)d_in[2];
    // d_in[3] is the causal mask -> known analytically, not read.
    float* O = (float*)d_out;

    dim3 grid(BH_TOTAL * (SEQ / BM));   // 32 heads * 16 m-blocks = 512 blocks
    fa_causal_fp32_kernel<<<grid, NTHREADS>>>(Q, K, V, O);
}